// round 16
// baseline (speedup 1.0000x reference)
#include <cuda_runtime.h>
#include <cstdint>

#define D 128
#define S 12
#define ITEMS_PER_TILE 4
#define MTILE 48             // 3 rowtiles x 16 rows; 6 warps = (rowtile, N-half)
#define NTHREADS 192
#define KSTEPS 8             // K=128, 16 per bf16 mma
#define FLDF 136             // bf16 feat row stride (elems)

// ---- scratch (allocation-free rule) ----
__device__ float g_agg_a[3200  * 128];
__device__ float g_agg_b[38400 * 128];
__device__ float g_agg_c[3200  * 128];

// SMEM layout (bytes)
#define NB_BYTES   (MTILE * D * 4)          // 24576 per buffer
#define FEAT_BYTES (MTILE * FLDF * 2)       // 13056 per buffer
#define BTAB_BYTES (KSTEPS * 8 * 32 * 16)   // 32768
#define OFF_NB   0
#define OFF_FEAT (2 * NB_BYTES)                      // 49152
#define OFF_BTAB (OFF_FEAT + 2 * FEAT_BYTES)         // 75264
#define OFF_W1B  (OFF_BTAB + BTAB_BYTES)             // 108032
#define OFF_W2S  (OFF_W1B + 512)
#define OFF_LGS  (OFF_W2S + 512)
#define SMEM_BYTES (OFF_LGS + 2 * MTILE * 4)         // ~109.4 KB

__device__ __forceinline__ uint32_t bf16x2(float lo, float hi) {
    uint32_t r;
    asm("cvt.rn.bf16x2.f32 %0, %1, %2;" : "=r"(r) : "f"(hi), "f"(lo));
    return r;
}
__device__ __forceinline__ void mma_bf16(float* d, uint32_t a0, uint32_t a1,
                                         uint32_t a2, uint32_t a3,
                                         uint32_t b0, uint32_t b1) {
    asm volatile(
        "mma.sync.aligned.m16n8k16.row.col.f32.bf16.bf16.f32 "
        "{%0,%1,%2,%3}, {%4,%5,%6,%7}, {%8,%9}, {%0,%1,%2,%3};"
        : "+f"(d[0]), "+f"(d[1]), "+f"(d[2]), "+f"(d[3])
        : "r"(a0), "r"(a1), "r"(a2), "r"(a3), "r"(b0), "r"(b1));
}
__device__ __forceinline__ float lrelu(float x) { return x > 0.f ? x : 0.2f * x; }
__device__ __forceinline__ void cp16(uint32_t smem_dst, const void* gsrc) {
    asm volatile("cp.async.cg.shared.global [%0], [%1], 16;" :: "r"(smem_dst), "l"(gsrc));
}
__device__ __forceinline__ void cp_commit() { asm volatile("cp.async.commit_group;"); }
__device__ __forceinline__ void cp_wait1() { asm volatile("cp.async.wait_group 1;" ::: "memory"); }
__device__ __forceinline__ uint32_t smem_u32(const void* p) {
    return (uint32_t)__cvta_generic_to_shared(p);
}

// Fused aggregate, two workloads per launch; 2 CTAs/SM; build(t+1) overlapped
// with MMA(t); 2 barriers per tile.
__global__ __launch_bounds__(NTHREADS, 2) void fused_agg_kernel(
    const float* __restrict__ itemA, const float* __restrict__ nbhA,
    const float* __restrict__ nbwA,  float* __restrict__ outA, int ntA,
    const float* __restrict__ itemB, const float* __restrict__ nbhB,
    const float* __restrict__ nbwB,  float* __restrict__ outB, int ntB,
    const float* __restrict__ w1,    const float* __restrict__ w2)
{
    extern __shared__ char sm[];
    float*    nbbuf = (float*)(sm + OFF_NB);        // [2][48*128] fp32 (epi only)
    uint16_t* featb = (uint16_t*)(sm + OFF_FEAT);   // [2][48][136] bf16
    uint4*    btab  = (uint4*)(sm + OFF_BTAB);      // [8][8][32]
    float*    w1b   = (float*)(sm + OFF_W1B);       // [128]
    float*    w2s   = (float*)(sm + OFF_W2S);       // [128]
    float*    lgs2  = (float*)(sm + OFF_LGS);       // [2][48]

    const int tid  = threadIdx.x;
    const int lane = tid & 31;
    const int warp = tid >> 5;
    const int c  = lane & 3;
    const int g  = lane >> 2;
    const int rt = warp >> 1;
    const int nh = warp & 1;
    const int m0 = rt * 16 + g;
    const int ntiles = ntA + ntB;

    // build-iter coords (fixed per thread)
    const int br = tid >> 5;            // base row for build (row = br + 6*i? no: idx scheme below)

    // ---- one-time: btab, bias row, w2 ----
    for (int idx = tid; idx < KSTEPS * 8 * 32; idx += NTHREADS) {
        const int t  = idx & 31;
        const int p  = (idx >> 5) & 7;
        const int ks = idx >> 8;
        const int tc = t & 3, tg = t >> 2;
        const int k0 = ks * 16 + 2 * tc;
        const int n0 = (2 * p) * 8 + tg;
        const int n1 = (2 * p + 1) * 8 + tg;
        uint4 v;
        v.x = bf16x2(w1[k0 * D + n0],       w1[(k0 + 1) * D + n0]);
        v.y = bf16x2(w1[(k0 + 8) * D + n0], w1[(k0 + 9) * D + n0]);
        v.z = bf16x2(w1[k0 * D + n1],       w1[(k0 + 1) * D + n1]);
        v.w = bf16x2(w1[(k0 + 8) * D + n1], w1[(k0 + 9) * D + n1]);
        btab[idx] = v;
    }
    if (tid < D) { w1b[tid] = w1[D * D + tid]; w2s[tid] = w2[tid]; }

    // resolve workload for tile T
    #define RESOLVE(T, IT, NB, NW, LT)                                            \
        const int LT##isA = (T) < ntA;                                            \
        const int LT = LT##isA ? (T) : (T) - ntA;                                 \
        const float* IT = LT##isA ? itemA : itemB;                                \
        const float* NB = LT##isA ? nbhA  : nbhB;                                 \
        const float* NW = LT##isA ? nbwA  : nbwB;

    #define PREFETCH_NB(NBp, LT, PB) do {                                         \
        const int _rb = (LT) * MTILE;                                             \
        float* _nbd = nbbuf + (PB) * (MTILE * D);                                 \
        _Pragma("unroll")                                                         \
        for (int _i = 0; _i < 8; _i++) {                                          \
            const int _idx = tid + _i * NTHREADS;                                 \
            const int _r = _idx >> 5, _l4 = _idx & 31;                            \
            cp16(smem_u32(&_nbd[_r * D + _l4 * 4]),                               \
                 (const float4*)(NBp) + (size_t)(_rb + _r) * 32 + _l4);           \
        }                                                                         \
    } while (0)

    int pb = 0, fb = 0;

    // ---- prologue: prefetch nb[t0] and build feat[0] for t0 ----
    if (blockIdx.x < ntiles) {
        RESOLVE(blockIdx.x, it0, nb0, nw0, lt0);
        PREFETCH_NB(nb0, lt0, 0);
        cp_commit();
        const int rb0 = lt0 * MTILE, ib0 = lt0 * ITEMS_PER_TILE;
        #pragma unroll
        for (int i = 0; i < 8; i++) {
            const int idx = tid + i * NTHREADS;
            const int r = idx >> 5, l4 = idx & 31;
            float4 a = __ldg((const float4*)nb0 + (size_t)(rb0 + r) * 32 + l4);
            float4 b = __ldg((const float4*)it0 + (size_t)(ib0 + (unsigned)r / 12u) * 32 + l4);
            uint2 pk;
            pk.x = bf16x2(a.x * b.x, a.y * b.y);
            pk.y = bf16x2(a.z * b.z, a.w * b.w);
            *(uint2*)&featb[r * FLDF + l4 * 4] = pk;
        }
    } else {
        cp_commit();
    }
    __syncthreads();

    for (int tile = blockIdx.x; tile < ntiles; tile += gridDim.x) {
        RESOLVE(tile, itC, nbC, nwC, ltC);
        float* outp = ltCisA ? outA : outB;
        const int itembase = ltC * ITEMS_PER_TILE;
        const int rbC = ltC * MTILE;

        // prefetch nb for next tile
        const int nxt = tile + gridDim.x;
        if (nxt < ntiles) {
            RESOLVE(nxt, itP, nbP, nwP, ltP);
            PREFETCH_NB(nbP, ltP, pb ^ 1);
        }
        cp_commit();

        // early nbw LDG (latency hidden under MMA loop)
        const float nbw0 = __ldg(&nwC[rbC + m0]);
        const float nbw1 = __ldg(&nwC[rbC + m0 + 8]);

        // next-tile (clamped) pointers for overlapped build
        const int tcl = (nxt < ntiles) ? nxt : (ntiles - 1);
        RESOLVE(tcl, itN, nbN, nwN, ltN);
        const int rbN = ltN * MTILE, ibN = ltN * ITEMS_PER_TILE;

        const uint16_t* featR = featb + fb * (MTILE * FLDF);
        uint16_t*       featW = featb + (fb ^ 1) * (MTILE * FLDF);

        // ---- fused: MMA(tile) + build feat(next) ----
        float acc[8][4];
        #pragma unroll
        for (int j = 0; j < 8; j++)
            #pragma unroll
            for (int q = 0; q < 4; q++) acc[j][q] = 0.f;

        #pragma unroll
        for (int ks = 0; ks < KSTEPS; ks++) {
            const int k0 = ks * 16 + 2 * c;
            const uint16_t* f0 = &featR[m0 * FLDF + k0];
            uint32_t a0 = *(const uint32_t*)(f0);
            uint32_t a1 = *(const uint32_t*)(f0 + 8 * FLDF);
            uint32_t a2 = *(const uint32_t*)(f0 + 8);
            uint32_t a3 = *(const uint32_t*)(f0 + 8 * FLDF + 8);
            const uint4* bks = &btab[ks * 256 + nh * 128];
            #pragma unroll
            for (int pp = 0; pp < 4; pp++) {
                uint4 b = bks[pp * 32 + lane];
                mma_bf16(acc[2 * pp],     a0, a1, a2, a3, b.x, b.y);
                mma_bf16(acc[2 * pp + 1], a0, a1, a2, a3, b.z, b.w);
            }
            // overlapped build iter for next tile
            {
                const int idx = tid + ks * NTHREADS;
                const int r = idx >> 5, l4 = idx & 31;
                float4 a = __ldg((const float4*)nbN + (size_t)(rbN + r) * 32 + l4);
                float4 b = __ldg((const float4*)itN + (size_t)(ibN + (unsigned)r / 12u) * 32 + l4);
                uint2 pk;
                pk.x = bf16x2(a.x * b.x, a.y * b.y);
                pk.y = bf16x2(a.z * b.z, a.w * b.w);
                *(uint2*)&featW[r * FLDF + l4 * 4] = pk;
            }
        }

        // ---- partial logits for this N-half ----
        {
            const int r0 = m0, r1 = m0 + 8;
            float l0 = 0.f, l1 = 0.f;
            #pragma unroll
            for (int j = 0; j < 8; j++) {
                const int jj = nh * 8 + j;
                float2 wb = *(const float2*)&w1b[jj * 8 + 2 * c];
                float2 wv = *(const float2*)&w2s[jj * 8 + 2 * c];
                l0 = fmaf(lrelu(fmaf(nbw0, wb.x, acc[j][0])), wv.x, l0);
                l0 = fmaf(lrelu(fmaf(nbw0, wb.y, acc[j][1])), wv.y, l0);
                l1 = fmaf(lrelu(fmaf(nbw1, wb.x, acc[j][2])), wv.x, l1);
                l1 = fmaf(lrelu(fmaf(nbw1, wb.y, acc[j][3])), wv.y, l1);
            }
            l0 += __shfl_xor_sync(0xffffffffu, l0, 1);
            l0 += __shfl_xor_sync(0xffffffffu, l0, 2);
            l1 += __shfl_xor_sync(0xffffffffu, l1, 1);
            l1 += __shfl_xor_sync(0xffffffffu, l1, 2);
            if (c == 0) { lgs2[nh * MTILE + r0] = l0; lgs2[nh * MTILE + r1] = l1; }
        }

        // nb[tile] complete + lgs2 visible
        cp_wait1();
        __syncthreads();

        // ---- epilogue: inline softmax + weighted sum from fp32 SMEM ----
        if (tid < ITEMS_PER_TILE * 32) {
            const int i = tid >> 5, l4 = tid & 31;
            const int base = i * S;
            float lg[S];
            #pragma unroll
            for (int s = 0; s < S; s++)
                lg[s] = lgs2[base + s] + lgs2[MTILE + base + s];
            float m = lg[0];
            #pragma unroll
            for (int s = 1; s < S; s++) m = fmaxf(m, lg[s]);
            float e[S]; float sum = 0.f;
            #pragma unroll
            for (int s = 0; s < S; s++) { e[s] = __expf(lg[s] - m); sum += e[s]; }
            const float inv = 1.f / sum;

            const float* nbp = &nbbuf[pb * (MTILE * D) + (i * S) * D + l4 * 4];
            float4 o = make_float4(0.f, 0.f, 0.f, 0.f);
            #pragma unroll
            for (int s = 0; s < S; s++) {
                float4 v = *(const float4*)&nbp[s * D];
                const float a = e[s] * inv;
                o.x = fmaf(a, v.x, o.x); o.y = fmaf(a, v.y, o.y);
                o.z = fmaf(a, v.z, o.z); o.w = fmaf(a, v.w, o.w);
            }
            *(float4*)&outp[(size_t)(itembase + i) * D + l4 * 4] = o;
        }
        __syncthreads();
        pb ^= 1; fb ^= 1;
    }
}

// ---- final gating: 8 warps x 4 items, SMEM-staged (w3,w4); grid 100 ----
#define FB_ITEMS 32
#define FIN_SMEM ((128 * 128 + FB_ITEMS * 128) * 8)

#define FMA2(acc, a, b) \
    asm("fma.rn.f32x2 %0, %1, %2, %0;" : "+l"(acc) : "l"(a), "l"(b))
__device__ __forceinline__ void unpack_f32(unsigned long long p, float& lo, float& hi) {
    asm("mov.b64 {%0, %1}, %2;" : "=f"(lo), "=f"(hi) : "l"(p));
}

__global__ __launch_bounds__(256, 1) void final_kernel(
    const float* __restrict__ hidden, const float* __restrict__ agg_a,
    const float* __restrict__ agg_c,  const float* __restrict__ w3,
    const float* __restrict__ w4,     const float* __restrict__ sv,
    float* __restrict__ out)
{
    extern __shared__ float2 fsm[];
    float2* wq = fsm;
    float2* hg = wq + 128 * 128;

    const int tid  = threadIdx.x;
    const int lane = tid & 31;
    const int warp = tid >> 5;
    const float s0 = sv[0], s1 = sv[1];

    for (int idx = tid; idx < 128 * 128; idx += 256)
        wq[idx] = make_float2(w3[idx], w4[idx]);

    const int ibase = blockIdx.x * FB_ITEMS;
    for (int idx = tid; idx < FB_ITEMS * 128; idx += 256) {
        const size_t off = (size_t)ibase * 128 + idx;
        hg[idx] = make_float2(hidden[off], s0 * agg_a[off] + s1 * agg_c[off]);
    }
    __syncthreads();

    const int i0 = warp * 4;
    unsigned long long acc[4][4];
    #pragma unroll
    for (int q = 0; q < 4; q++)
        #pragma unroll
        for (int j = 0; j < 4; j++) acc[q][j] = 0ULL;

    #pragma unroll 2
    for (int k = 0; k < 128; k++) {
        const float2* wrow = &wq[k * 128 + lane];
        unsigned long long wv0 = *(const unsigned long long*)&wrow[0];
        unsigned long long wv1 = *(const unsigned long long*)&wrow[32];
        unsigned long long wv2 = *(const unsigned long long*)&wrow[64];
        unsigned long long wv3 = *(const unsigned long long*)&wrow[96];
        #pragma unroll
        for (int q = 0; q < 4; q++) {
            unsigned long long hq = *(const unsigned long long*)&hg[(i0 + q) * 128 + k];
            FMA2(acc[q][0], hq, wv0);
            FMA2(acc[q][1], hq, wv1);
            FMA2(acc[q][2], hq, wv2);
            FMA2(acc[q][3], hq, wv3);
        }
    }
    #pragma unroll
    for (int q = 0; q < 4; q++) {
        const int n = ibase + i0 + q;
        #pragma unroll
        for (int j = 0; j < 4; j++) {
            const int col = lane + 32 * j;
            float a0, a1;
            unpack_f32(acc[q][j], a0, a1);
            const float wgt = 1.f / (1.f + __expf(-(a0 + a1)));
            float2 v = hg[(i0 + q) * 128 + col];
            out[(size_t)n * 128 + col] = (1.f - wgt) * v.x + wgt * v.y;
        }
    }
}

extern "C" void kernel_launch(void* const* d_in, const int* in_sizes, int n_in,
                              void* d_out, int out_size)
{
    const float* hidden = (const float*)d_in[0];
    const float* nh1    = (const float*)d_in[1];
    const float* nh2    = (const float*)d_in[2];
    const float* nw0    = (const float*)d_in[3];
    const float* nw1    = (const float*)d_in[4];
    const float* w1     = (const float*)d_in[5];
    const float* w2     = (const float*)d_in[6];
    const float* w3     = (const float*)d_in[7];
    const float* w4     = (const float*)d_in[8];
    const float* sv     = (const float*)d_in[9];
    float* out = (float*)d_out;

    float *agg_a, *agg_b, *agg_c;
    cudaGetSymbolAddress((void**)&agg_a, g_agg_a);
    cudaGetSymbolAddress((void**)&agg_b, g_agg_b);
    cudaGetSymbolAddress((void**)&agg_c, g_agg_c);

    cudaFuncSetAttribute(fused_agg_kernel,
                         cudaFuncAttributeMaxDynamicSharedMemorySize, SMEM_BYTES);
    cudaFuncSetAttribute(final_kernel,
                         cudaFuncAttributeMaxDynamicSharedMemorySize, FIN_SMEM);

    const int GP = 296;                      // 2 CTAs per SM
    const int T0 = 3200  / ITEMS_PER_TILE;   // 800 tiles
    const int T1 = 38400 / ITEMS_PER_TILE;   // 9600 tiles

    // hop 1: both levels merged (A = big, B = small)
    fused_agg_kernel<<<GP, NTHREADS, SMEM_BYTES>>>(
        nh1, nh2, nw1, agg_b, T1,
        hidden, nh1, nw0, agg_a, T0,
        w1, w2);
    // hop 2
    fused_agg_kernel<<<GP, NTHREADS, SMEM_BYTES>>>(
        agg_a, agg_b, nw0, agg_c, T0,
        agg_a, agg_b, nw0, agg_c, 0,
        w1, w2);
    // gate
    final_kernel<<<100, 256, FIN_SMEM>>>(hidden, agg_a, agg_c, w3, w4, sv, out);
}